// round 1
// baseline (speedup 1.0000x reference)
#include <cuda_runtime.h>
#include <math.h>

#define BSZ  4
#define TLEN 4096
#define CDIM 1024
#define HDIM 64

// Scratch for projected Q, K, V: [B*T, H] each (4 MB each)
__device__ float g_Q[BSZ * TLEN * HDIM];
__device__ float g_K[BSZ * TLEN * HDIM];
__device__ float g_V[BSZ * TLEN * HDIM];

// ---------------------------------------------------------------------------
// Projection: out[m, h] = sum_c x[m, c] * W[h, c]
// M = B*T = 16384, N = 64 (per weight), K = 1024.
// BM=128, BN=64, BK=32, 256 threads, 8x4 register tile per thread.
// grid = (128, 3): blockIdx.y selects Q/K/V.
// ---------------------------------------------------------------------------
__global__ __launch_bounds__(256) void proj_kernel(
    const float* __restrict__ x,
    const float* __restrict__ Wk,
    const float* __restrict__ Wq,
    const float* __restrict__ Wv)
{
    __shared__ float Xs[128][33];
    __shared__ float Ws[64][33];

    const int which = blockIdx.y;
    const float* __restrict__ W = (which == 0) ? Wq : (which == 1) ? Wk : Wv;
    float* __restrict__ outp    = (which == 0) ? g_Q : (which == 1) ? g_K : g_V;

    const int m0  = blockIdx.x * 128;
    const int tid = threadIdx.x;
    const int r0  = (tid >> 4) * 8;   // 16 row-groups x 8 rows
    const int c0  = (tid & 15) * 4;   // 16 col-groups x 4 cols

    float acc[8][4];
#pragma unroll
    for (int i = 0; i < 8; i++)
#pragma unroll
        for (int j = 0; j < 4; j++) acc[i][j] = 0.0f;

    for (int kc = 0; kc < CDIM; kc += 32) {
        // Load X tile: 128x32 floats = 1024 float4, 4 per thread
#pragma unroll
        for (int l = 0; l < 4; l++) {
            int idx = tid + l * 256;
            int row = idx >> 3;
            int p   = idx & 7;
            float4 v = *(const float4*)(x + (size_t)(m0 + row) * CDIM + kc + p * 4);
            Xs[row][p * 4 + 0] = v.x;
            Xs[row][p * 4 + 1] = v.y;
            Xs[row][p * 4 + 2] = v.z;
            Xs[row][p * 4 + 3] = v.w;
        }
        // Load W tile: 64x32 floats = 512 float4, 2 per thread
#pragma unroll
        for (int l = 0; l < 2; l++) {
            int idx = tid + l * 256;
            int row = idx >> 3;
            int p   = idx & 7;
            float4 v = *(const float4*)(W + (size_t)row * CDIM + kc + p * 4);
            Ws[row][p * 4 + 0] = v.x;
            Ws[row][p * 4 + 1] = v.y;
            Ws[row][p * 4 + 2] = v.z;
            Ws[row][p * 4 + 3] = v.w;
        }
        __syncthreads();

#pragma unroll 8
        for (int k = 0; k < 32; k++) {
            float a[8], b[4];
#pragma unroll
            for (int i = 0; i < 8; i++) a[i] = Xs[r0 + i][k];
#pragma unroll
            for (int j = 0; j < 4; j++) b[j] = Ws[c0 + j][k];
#pragma unroll
            for (int i = 0; i < 8; i++)
#pragma unroll
                for (int j = 0; j < 4; j++) acc[i][j] += a[i] * b[j];
        }
        __syncthreads();
    }

#pragma unroll
    for (int i = 0; i < 8; i++)
#pragma unroll
        for (int j = 0; j < 4; j++)
            outp[(size_t)(m0 + r0 + i) * HDIM + c0 + j] = acc[i][j];
}

// ---------------------------------------------------------------------------
// Causal flash attention.
// One CTA handles BM=64 query rows; iterates key blocks BN=64 up to diagonal.
// 128 threads; per-thread 8x4 tile of S and of O.
// grid = (64, 4); qb is reversed so long CTAs launch first.
// Dynamic smem: Qs, Ks, Vs, Ps each 64 x 65 floats.
// ---------------------------------------------------------------------------
__global__ __launch_bounds__(128) void attn_kernel(float* __restrict__ out)
{
    extern __shared__ float sm[];
    float* Qs = sm;               // 64*65
    float* Ks = Qs + 64 * 65;
    float* Vs = Ks + 64 * 65;
    float* Ps = Vs + 64 * 65;

    const int b   = blockIdx.y;
    const int qb  = gridDim.x - 1 - blockIdx.x;  // longest work first
    const int tid = threadIdx.x;
    const int r0  = (tid >> 4) * 8;   // 8 row-groups x 8 rows = 64
    const int c0  = (tid & 15) * 4;   // 16 col-groups x 4 cols = 64
    const float scale = 0.125f;        // H^-0.5

    // Load Q tile, pre-scaled
    {
        const float* Qg = g_Q + (size_t)(b * TLEN + qb * 64) * HDIM;
#pragma unroll
        for (int l = 0; l < 8; l++) {
            int idx = tid + l * 128;
            int row = idx >> 4;
            int p   = idx & 15;
            float4 v = *(const float4*)(Qg + row * HDIM + p * 4);
            Qs[row * 65 + p * 4 + 0] = v.x * scale;
            Qs[row * 65 + p * 4 + 1] = v.y * scale;
            Qs[row * 65 + p * 4 + 2] = v.z * scale;
            Qs[row * 65 + p * 4 + 3] = v.w * scale;
        }
    }

    float o[8][4];
    float mrow[8], lrow[8];
#pragma unroll
    for (int i = 0; i < 8; i++) {
        mrow[i] = -1e30f;
        lrow[i] = 0.0f;
#pragma unroll
        for (int j = 0; j < 4; j++) o[i][j] = 0.0f;
    }

    for (int jb = 0; jb <= qb; jb++) {
        // Load K, V tiles
        {
            const float* Kg = g_K + (size_t)(b * TLEN + jb * 64) * HDIM;
            const float* Vg = g_V + (size_t)(b * TLEN + jb * 64) * HDIM;
#pragma unroll
            for (int l = 0; l < 8; l++) {
                int idx = tid + l * 128;
                int row = idx >> 4;
                int p   = idx & 15;
                float4 kv = *(const float4*)(Kg + row * HDIM + p * 4);
                Ks[row * 65 + p * 4 + 0] = kv.x;
                Ks[row * 65 + p * 4 + 1] = kv.y;
                Ks[row * 65 + p * 4 + 2] = kv.z;
                Ks[row * 65 + p * 4 + 3] = kv.w;
                float4 vv = *(const float4*)(Vg + row * HDIM + p * 4);
                Vs[row * 65 + p * 4 + 0] = vv.x;
                Vs[row * 65 + p * 4 + 1] = vv.y;
                Vs[row * 65 + p * 4 + 2] = vv.z;
                Vs[row * 65 + p * 4 + 3] = vv.w;
            }
        }
        __syncthreads();

        // S = Q K^T  (per-thread 8x4 tile)
        float s[8][4];
#pragma unroll
        for (int i = 0; i < 8; i++)
#pragma unroll
            for (int j = 0; j < 4; j++) s[i][j] = 0.0f;

#pragma unroll 8
        for (int k = 0; k < 64; k++) {
            float a[8], bb[4];
#pragma unroll
            for (int i = 0; i < 8; i++) a[i] = Qs[(r0 + i) * 65 + k];
#pragma unroll
            for (int j = 0; j < 4; j++) bb[j] = Ks[(c0 + j) * 65 + k];
#pragma unroll
            for (int i = 0; i < 8; i++)
#pragma unroll
                for (int j = 0; j < 4; j++) s[i][j] += a[i] * bb[j];
        }

        // Causal mask on the diagonal block
        if (jb == qb) {
#pragma unroll
            for (int i = 0; i < 8; i++)
#pragma unroll
                for (int j = 0; j < 4; j++)
                    if (c0 + j > r0 + i) s[i][j] = -1e30f;
        }

        // Online softmax update (row stats across 16 lanes of a row group)
#pragma unroll
        for (int i = 0; i < 8; i++) {
            float mloc = fmaxf(fmaxf(s[i][0], s[i][1]), fmaxf(s[i][2], s[i][3]));
#pragma unroll
            for (int d = 1; d < 16; d <<= 1)
                mloc = fmaxf(mloc, __shfl_xor_sync(0xffffffffu, mloc, d));
            float mn = fmaxf(mrow[i], mloc);
            float al = __expf(mrow[i] - mn);
            float rs = 0.0f;
#pragma unroll
            for (int j = 0; j < 4; j++) {
                float p = __expf(s[i][j] - mn);
                Ps[(r0 + i) * 65 + c0 + j] = p;
                rs += p;
            }
#pragma unroll
            for (int d = 1; d < 16; d <<= 1)
                rs += __shfl_xor_sync(0xffffffffu, rs, d);
            lrow[i] = lrow[i] * al + rs;
#pragma unroll
            for (int j = 0; j < 4; j++) o[i][j] *= al;
            mrow[i] = mn;
        }
        __syncthreads();

        // O += P @ V  (per-thread 8 rows x 4 head dims; d0 == c0)
#pragma unroll 8
        for (int k = 0; k < 64; k++) {
            float pv[8], vb[4];
#pragma unroll
            for (int i = 0; i < 8; i++) pv[i] = Ps[(r0 + i) * 65 + k];
#pragma unroll
            for (int j = 0; j < 4; j++) vb[j] = Vs[k * 65 + c0 + j];
#pragma unroll
            for (int i = 0; i < 8; i++)
#pragma unroll
                for (int j = 0; j < 4; j++) o[i][j] += pv[i] * vb[j];
        }
        __syncthreads();
    }

    // Normalize and write out [B, T, H]
    float* Og = out + (size_t)(b * TLEN + qb * 64) * HDIM;
#pragma unroll
    for (int i = 0; i < 8; i++) {
        float rinv = 1.0f / lrow[i];
#pragma unroll
        for (int j = 0; j < 4; j++)
            Og[(r0 + i) * HDIM + c0 + j] = o[i][j] * rinv;
    }
}

// ---------------------------------------------------------------------------
// Inputs (metadata order): x [B,T,C] f32, mask [T,T] i32 (ignored: standard
// causal tril), Wk [H,C] f32, Wq [H,C] f32, Wv [H,C] f32.
// Output: [B,T,H] f32.
// ---------------------------------------------------------------------------
extern "C" void kernel_launch(void* const* d_in, const int* in_sizes, int n_in,
                              void* d_out, int out_size)
{
    const float* x  = (const float*)d_in[0];
    const float* Wk = (const float*)d_in[2];
    const float* Wq = (const float*)d_in[3];
    const float* Wv = (const float*)d_in[4];
    float* out = (float*)d_out;

    dim3 gp(128, 3);
    proj_kernel<<<gp, 256>>>(x, Wk, Wq, Wv);

    const int smem_bytes = 4 * 64 * 65 * (int)sizeof(float);  // 66560
    cudaFuncSetAttribute(attn_kernel,
                         cudaFuncAttributeMaxDynamicSharedMemorySize, smem_bytes);
    dim3 ga(64, 4);
    attn_kernel<<<ga, 128, smem_bytes>>>(out);
}

// round 2
// speedup vs baseline: 1.0961x; 1.0961x over previous
#include <cuda_runtime.h>
#include <math.h>

#define BSZ  4
#define TLEN 4096
#define CDIM 1024
#define HDIM 64
#define MTOT (BSZ * TLEN)

// Projected operands. Q and K are stored TRANSPOSED [h][m] so the attention
// kernel can use LDS.128 for all GEMM operands. Q is pre-scaled by H^-0.5.
__device__ float g_Qt[HDIM * MTOT];
__device__ float g_Kt[HDIM * MTOT];
__device__ float g_V [MTOT * HDIM];

typedef unsigned long long u64;

__device__ __forceinline__ u64 splat2(float x) {
    u64 r; asm("mov.b64 %0, {%1, %1};" : "=l"(r) : "f"(x)); return r;
}
__device__ __forceinline__ u64 pack2(float x, float y) {
    u64 r; asm("mov.b64 %0, {%1, %2};" : "=l"(r) : "f"(x), "f"(y)); return r;
}
__device__ __forceinline__ float2 unpack2(u64 v) {
    float2 f; asm("mov.b64 {%0, %1}, %2;" : "=f"(f.x), "=f"(f.y) : "l"(v)); return f;
}
__device__ __forceinline__ void ffma2(u64 &d, u64 a, u64 b) {
    asm("fma.rn.f32x2 %0, %1, %2, %0;" : "+l"(d) : "l"(a), "l"(b));
}
__device__ __forceinline__ u64 mul2(u64 a, u64 b) {
    u64 r; asm("mul.rn.f32x2 %0, %1, %2;" : "=l"(r) : "l"(a), "l"(b)); return r;
}

// ---------------------------------------------------------------------------
// Projection: out[m,h] = sum_c x[m,c] * W[h,c].  M=16384, N=64, K=1024.
// BM=128, BN=64, BK=32, 256 threads, 8x4 tile, f32x2 pairs along m.
// Xt tile is stored transposed+swizzled in smem; Wt transposed (pitch 68).
// which: 0 -> Qt (scaled, transposed out), 1 -> Kt (transposed out), 2 -> V.
// ---------------------------------------------------------------------------
__global__ __launch_bounds__(256) void proj_kernel(
    const float* __restrict__ x,
    const float* __restrict__ Wk,
    const float* __restrict__ Wq,
    const float* __restrict__ Wv)
{
    __shared__ float Xt[32 * 128];   // swizzled [c][m]
    __shared__ float Wt[32 * 68];    // [c][h]

    const int which = blockIdx.y;
    const float* __restrict__ W = (which == 0) ? Wq : (which == 1) ? Wk : Wv;

    const int m0  = blockIdx.x * 128;
    const int tid = threadIdx.x;
    const int r0  = (tid >> 4) * 8;
    const int c0  = (tid & 15) * 4;
    const int rg  = r0 >> 2;

    u64 acc2[4][4];
#pragma unroll
    for (int u = 0; u < 4; u++)
#pragma unroll
        for (int j = 0; j < 4; j++) acc2[u][j] = 0ull;

    for (int kc = 0; kc < CDIM; kc += 32) {
        // X tile 128x32 -> transposed swizzled Xt[c][m]
#pragma unroll
        for (int l = 0; l < 4; l++) {
            int idx = tid + l * 256;
            int row = idx >> 3;          // m-local
            int p   = idx & 7;           // c-group
            float4 v = *(const float4*)(x + (size_t)(m0 + row) * CDIM + kc + p * 4);
            int mg = row >> 2, ml = row & 3;
            int cc = p * 4;
            Xt[(cc + 0) * 128 + (((mg) ^ (cc + 0)) << 2) + ml] = v.x;
            Xt[(cc + 1) * 128 + (((mg) ^ (cc + 1)) << 2) + ml] = v.y;
            Xt[(cc + 2) * 128 + (((mg) ^ (cc + 2)) << 2) + ml] = v.z;
            Xt[(cc + 3) * 128 + (((mg) ^ (cc + 3)) << 2) + ml] = v.w;
        }
        // W tile 64x32 -> transposed Wt[c][h]
#pragma unroll
        for (int l = 0; l < 2; l++) {
            int idx = tid + l * 256;
            int row = idx >> 3;          // h
            int p   = idx & 7;           // c-group
            float4 v = *(const float4*)(W + (size_t)row * CDIM + kc + p * 4);
            Wt[(p * 4 + 0) * 68 + row] = v.x;
            Wt[(p * 4 + 1) * 68 + row] = v.y;
            Wt[(p * 4 + 2) * 68 + row] = v.z;
            Wt[(p * 4 + 3) * 68 + row] = v.w;
        }
        __syncthreads();

#pragma unroll 8
        for (int k = 0; k < 32; k++) {
            ulonglong2 A0 = *(const ulonglong2*)&Xt[k * 128 + ((rg ^ k) << 2)];
            ulonglong2 A1 = *(const ulonglong2*)&Xt[k * 128 + (((rg + 1) ^ k) << 2)];
            float4 bf = *(const float4*)&Wt[k * 68 + c0];
            u64 b0 = splat2(bf.x), b1 = splat2(bf.y), b2 = splat2(bf.z), b3 = splat2(bf.w);
            ffma2(acc2[0][0], A0.x, b0); ffma2(acc2[0][1], A0.x, b1);
            ffma2(acc2[0][2], A0.x, b2); ffma2(acc2[0][3], A0.x, b3);
            ffma2(acc2[1][0], A0.y, b0); ffma2(acc2[1][1], A0.y, b1);
            ffma2(acc2[1][2], A0.y, b2); ffma2(acc2[1][3], A0.y, b3);
            ffma2(acc2[2][0], A1.x, b0); ffma2(acc2[2][1], A1.x, b1);
            ffma2(acc2[2][2], A1.x, b2); ffma2(acc2[2][3], A1.x, b3);
            ffma2(acc2[3][0], A1.y, b0); ffma2(acc2[3][1], A1.y, b1);
            ffma2(acc2[3][2], A1.y, b2); ffma2(acc2[3][3], A1.y, b3);
        }
        __syncthreads();
    }

    // Unpack accumulators
    float acc[8][4];
#pragma unroll
    for (int u = 0; u < 4; u++)
#pragma unroll
        for (int j = 0; j < 4; j++) {
            float2 f = unpack2(acc2[u][j]);
            acc[2 * u + 0][j] = f.x;
            acc[2 * u + 1][j] = f.y;
        }

    if (which == 0) {
#pragma unroll
        for (int i = 0; i < 8; i++)
#pragma unroll
            for (int j = 0; j < 4; j++) acc[i][j] *= 0.125f;  // H^-0.5 folded in
    }

    if (which <= 1) {
        float* outT = (which == 0) ? g_Qt : g_Kt;
#pragma unroll
        for (int j = 0; j < 4; j++) {
            float4 lo = make_float4(acc[0][j], acc[1][j], acc[2][j], acc[3][j]);
            float4 hi = make_float4(acc[4][j], acc[5][j], acc[6][j], acc[7][j]);
            *(float4*)&outT[(size_t)(c0 + j) * MTOT + m0 + r0]     = lo;
            *(float4*)&outT[(size_t)(c0 + j) * MTOT + m0 + r0 + 4] = hi;
        }
    } else {
#pragma unroll
        for (int i = 0; i < 8; i++)
            *(float4*)&g_V[(size_t)(m0 + r0 + i) * HDIM + c0] =
                make_float4(acc[i][0], acc[i][1], acc[i][2], acc[i][3]);
    }
}

// ---------------------------------------------------------------------------
// Causal flash attention. BM=BN=64, 128 threads, 8x4 tile, f32x2 along rows.
// Qt/Kt tiles come pre-transposed from gmem; Pt transposed in smem (swizzled).
// ---------------------------------------------------------------------------
__global__ __launch_bounds__(128) void attn_kernel(float* __restrict__ out)
{
    extern __shared__ float sm[];
    float* Qt = sm;                 // [h][row]   64 x 68
    float* Kt = Qt + 64 * 68;       // [h][key]   64 x 68
    float* Vs = Kt + 64 * 68;       // [key][h]   64 x 68
    float* Pt = Vs + 64 * 68;       // [key][row] 64 x 64, XOR swizzled

    const int b   = blockIdx.y;
    const int qb  = gridDim.x - 1 - blockIdx.x;
    const int tid = threadIdx.x;
    const int r0  = (tid >> 4) * 8;
    const int c0  = (tid & 15) * 4;
    const int rg  = r0 >> 2;
    const int m0  = b * TLEN + qb * 64;

    // Q tile (already scaled): rows h, cols m
#pragma unroll
    for (int l = 0; l < 8; l++) {
        int idx = tid + l * 128;
        int h = idx >> 4, p = idx & 15;
        *(float4*)&Qt[h * 68 + p * 4] = *(const float4*)&g_Qt[(size_t)h * MTOT + m0 + p * 4];
    }

    u64 o2[4][4];
    float mrow[8], lrow[8];
#pragma unroll
    for (int u = 0; u < 4; u++)
#pragma unroll
        for (int j = 0; j < 4; j++) o2[u][j] = 0ull;
#pragma unroll
    for (int i = 0; i < 8; i++) { mrow[i] = -1e30f; lrow[i] = 0.0f; }

    for (int jb = 0; jb <= qb; jb++) {
        const int kb = b * TLEN + jb * 64;
#pragma unroll
        for (int l = 0; l < 8; l++) {
            int idx = tid + l * 128;
            int row = idx >> 4, p = idx & 15;
            *(float4*)&Kt[row * 68 + p * 4] = *(const float4*)&g_Kt[(size_t)row * MTOT + kb + p * 4];
            *(float4*)&Vs[row * 68 + p * 4] = *(const float4*)&g_V[(size_t)(kb + row) * HDIM + p * 4];
        }
        __syncthreads();

        // S = Q^T-tiles: s2[u][j], pairs along rows
        u64 s2[4][4];
#pragma unroll
        for (int u = 0; u < 4; u++)
#pragma unroll
            for (int j = 0; j < 4; j++) s2[u][j] = 0ull;

#pragma unroll 8
        for (int k = 0; k < 64; k++) {
            ulonglong2 A0 = *(const ulonglong2*)&Qt[k * 68 + r0];
            ulonglong2 A1 = *(const ulonglong2*)&Qt[k * 68 + r0 + 4];
            float4 bf = *(const float4*)&Kt[k * 68 + c0];
            u64 b0 = splat2(bf.x), b1 = splat2(bf.y), b2 = splat2(bf.z), b3 = splat2(bf.w);
            ffma2(s2[0][0], A0.x, b0); ffma2(s2[0][1], A0.x, b1);
            ffma2(s2[0][2], A0.x, b2); ffma2(s2[0][3], A0.x, b3);
            ffma2(s2[1][0], A0.y, b0); ffma2(s2[1][1], A0.y, b1);
            ffma2(s2[1][2], A0.y, b2); ffma2(s2[1][3], A0.y, b3);
            ffma2(s2[2][0], A1.x, b0); ffma2(s2[2][1], A1.x, b1);
            ffma2(s2[2][2], A1.x, b2); ffma2(s2[2][3], A1.x, b3);
            ffma2(s2[3][0], A1.y, b0); ffma2(s2[3][1], A1.y, b1);
            ffma2(s2[3][2], A1.y, b2); ffma2(s2[3][3], A1.y, b3);
        }

        // Unpack S
        float s[8][4];
#pragma unroll
        for (int u = 0; u < 4; u++)
#pragma unroll
            for (int j = 0; j < 4; j++) {
                float2 f = unpack2(s2[u][j]);
                s[2 * u + 0][j] = f.x;
                s[2 * u + 1][j] = f.y;
            }

        if (jb == qb) {
#pragma unroll
            for (int i = 0; i < 8; i++)
#pragma unroll
                for (int j = 0; j < 4; j++)
                    if (c0 + j > r0 + i) s[i][j] = -1e30f;
        }

        // Online softmax
        float al[8], p[8][4];
#pragma unroll
        for (int i = 0; i < 8; i++) {
            float mloc = fmaxf(fmaxf(s[i][0], s[i][1]), fmaxf(s[i][2], s[i][3]));
#pragma unroll
            for (int d = 1; d < 16; d <<= 1)
                mloc = fmaxf(mloc, __shfl_xor_sync(0xffffffffu, mloc, d));
            float mn = fmaxf(mrow[i], mloc);
            al[i] = __expf(mrow[i] - mn);
            float rs = 0.0f;
#pragma unroll
            for (int j = 0; j < 4; j++) {
                p[i][j] = __expf(s[i][j] - mn);
                rs += p[i][j];
            }
#pragma unroll
            for (int d = 1; d < 16; d <<= 1)
                rs += __shfl_xor_sync(0xffffffffu, rs, d);
            lrow[i] = lrow[i] * al[i] + rs;
            mrow[i] = mn;
        }
#pragma unroll
        for (int u = 0; u < 4; u++) {
            u64 a2 = pack2(al[2 * u], al[2 * u + 1]);
#pragma unroll
            for (int j = 0; j < 4; j++) o2[u][j] = mul2(o2[u][j], a2);
        }

        // Store P transposed (swizzled): Pt[key][row]
#pragma unroll
        for (int j = 0; j < 4; j++) {
            int key = c0 + j;
            int sw0 = ((rg ^ (key & 15)) << 2);
            int sw1 = (((rg + 1) ^ (key & 15)) << 2);
            *(float4*)&Pt[key * 64 + sw0] = make_float4(p[0][j], p[1][j], p[2][j], p[3][j]);
            *(float4*)&Pt[key * 64 + sw1] = make_float4(p[4][j], p[5][j], p[6][j], p[7][j]);
        }
        __syncthreads();

        // O += P @ V
#pragma unroll 8
        for (int k = 0; k < 64; k++) {
            ulonglong2 A0 = *(const ulonglong2*)&Pt[k * 64 + ((rg ^ (k & 15)) << 2)];
            ulonglong2 A1 = *(const ulonglong2*)&Pt[k * 64 + (((rg + 1) ^ (k & 15)) << 2)];
            float4 vf = *(const float4*)&Vs[k * 68 + c0];
            u64 b0 = splat2(vf.x), b1 = splat2(vf.y), b2 = splat2(vf.z), b3 = splat2(vf.w);
            ffma2(o2[0][0], A0.x, b0); ffma2(o2[0][1], A0.x, b1);
            ffma2(o2[0][2], A0.x, b2); ffma2(o2[0][3], A0.x, b3);
            ffma2(o2[1][0], A0.y, b0); ffma2(o2[1][1], A0.y, b1);
            ffma2(o2[1][2], A0.y, b2); ffma2(o2[1][3], A0.y, b3);
            ffma2(o2[2][0], A1.x, b0); ffma2(o2[2][1], A1.x, b1);
            ffma2(o2[2][2], A1.x, b2); ffma2(o2[2][3], A1.x, b3);
            ffma2(o2[3][0], A1.y, b0); ffma2(o2[3][1], A1.y, b1);
            ffma2(o2[3][2], A1.y, b2); ffma2(o2[3][3], A1.y, b3);
        }
        __syncthreads();
    }

    // Normalize, write out [B,T,H]
    float o[8][4];
#pragma unroll
    for (int u = 0; u < 4; u++)
#pragma unroll
        for (int j = 0; j < 4; j++) {
            float2 f = unpack2(o2[u][j]);
            o[2 * u + 0][j] = f.x;
            o[2 * u + 1][j] = f.y;
        }
#pragma unroll
    for (int i = 0; i < 8; i++) {
        float rinv = 1.0f / lrow[i];
        *(float4*)&out[(size_t)(m0 + r0 + i) * HDIM + c0] =
            make_float4(o[i][0] * rinv, o[i][1] * rinv, o[i][2] * rinv, o[i][3] * rinv);
    }
}

// ---------------------------------------------------------------------------
extern "C" void kernel_launch(void* const* d_in, const int* in_sizes, int n_in,
                              void* d_out, int out_size)
{
    const float* x  = (const float*)d_in[0];
    const float* Wk = (const float*)d_in[2];
    const float* Wq = (const float*)d_in[3];
    const float* Wv = (const float*)d_in[4];
    float* out = (float*)d_out;

    dim3 gp(128, 3);
    proj_kernel<<<gp, 256>>>(x, Wk, Wq, Wv);

    const int smem_bytes = (3 * 64 * 68 + 64 * 64) * (int)sizeof(float);  // 68608
    cudaFuncSetAttribute(attn_kernel,
                         cudaFuncAttributeMaxDynamicSharedMemorySize, smem_bytes);
    dim3 ga(64, 4);
    attn_kernel<<<ga, 128, smem_bytes>>>(out);
}

// round 3
// speedup vs baseline: 1.3295x; 1.2130x over previous
#include <cuda_runtime.h>
#include <math.h>

#define BSZ  4
#define TLEN 4096
#define CDIM 1024
#define HDIM 64
#define MTOT (BSZ * TLEN)
#define NSPLIT 2

// Projected operands. Q and K stored TRANSPOSED [h][m]; Q pre-scaled by H^-0.5.
__device__ float g_Qt[HDIM * MTOT];
__device__ float g_Kt[HDIM * MTOT];
__device__ float g_V [MTOT * HDIM];
// Split-KV partials: unnormalized O and (m, l) stats per split.
__device__ float  g_Opart[NSPLIT * MTOT * HDIM];
__device__ float2 g_stats[NSPLIT * MTOT];

typedef unsigned long long u64;

__device__ __forceinline__ u64 splat2(float x) {
    u64 r; asm("mov.b64 %0, {%1, %1};" : "=l"(r) : "f"(x)); return r;
}
__device__ __forceinline__ u64 pack2(float x, float y) {
    u64 r; asm("mov.b64 %0, {%1, %2};" : "=l"(r) : "f"(x), "f"(y)); return r;
}
__device__ __forceinline__ float2 unpack2(u64 v) {
    float2 f; asm("mov.b64 {%0, %1}, %2;" : "=f"(f.x), "=f"(f.y) : "l"(v)); return f;
}
__device__ __forceinline__ void ffma2(u64 &d, u64 a, u64 b) {
    asm("fma.rn.f32x2 %0, %1, %2, %0;" : "+l"(d) : "l"(a), "l"(b));
}
__device__ __forceinline__ u64 mul2(u64 a, u64 b) {
    u64 r; asm("mul.rn.f32x2 %0, %1, %2;" : "=l"(r) : "l"(a), "l"(b)); return r;
}

// ---------------------------------------------------------------------------
// Projection (unchanged; at fp32 roofline). out[m,h] = sum_c x[m,c]*W[h,c].
// ---------------------------------------------------------------------------
__global__ __launch_bounds__(256) void proj_kernel(
    const float* __restrict__ x,
    const float* __restrict__ Wk,
    const float* __restrict__ Wq,
    const float* __restrict__ Wv)
{
    __shared__ float Xt[32 * 128];
    __shared__ float Wt[32 * 68];

    const int which = blockIdx.y;
    const float* __restrict__ W = (which == 0) ? Wq : (which == 1) ? Wk : Wv;

    const int m0  = blockIdx.x * 128;
    const int tid = threadIdx.x;
    const int r0  = (tid >> 4) * 8;
    const int c0  = (tid & 15) * 4;
    const int rg  = r0 >> 2;

    u64 acc2[4][4];
#pragma unroll
    for (int u = 0; u < 4; u++)
#pragma unroll
        for (int j = 0; j < 4; j++) acc2[u][j] = 0ull;

    for (int kc = 0; kc < CDIM; kc += 32) {
#pragma unroll
        for (int l = 0; l < 4; l++) {
            int idx = tid + l * 256;
            int row = idx >> 3;
            int p   = idx & 7;
            float4 v = *(const float4*)(x + (size_t)(m0 + row) * CDIM + kc + p * 4);
            int mg = row >> 2, ml = row & 3;
            int cc = p * 4;
            Xt[(cc + 0) * 128 + ((mg ^ (cc + 0)) << 2) + ml] = v.x;
            Xt[(cc + 1) * 128 + ((mg ^ (cc + 1)) << 2) + ml] = v.y;
            Xt[(cc + 2) * 128 + ((mg ^ (cc + 2)) << 2) + ml] = v.z;
            Xt[(cc + 3) * 128 + ((mg ^ (cc + 3)) << 2) + ml] = v.w;
        }
#pragma unroll
        for (int l = 0; l < 2; l++) {
            int idx = tid + l * 256;
            int row = idx >> 3;
            int p   = idx & 7;
            float4 v = *(const float4*)(W + (size_t)row * CDIM + kc + p * 4);
            Wt[(p * 4 + 0) * 68 + row] = v.x;
            Wt[(p * 4 + 1) * 68 + row] = v.y;
            Wt[(p * 4 + 2) * 68 + row] = v.z;
            Wt[(p * 4 + 3) * 68 + row] = v.w;
        }
        __syncthreads();

#pragma unroll 8
        for (int k = 0; k < 32; k++) {
            ulonglong2 A0 = *(const ulonglong2*)&Xt[k * 128 + ((rg ^ k) << 2)];
            ulonglong2 A1 = *(const ulonglong2*)&Xt[k * 128 + (((rg + 1) ^ k) << 2)];
            float4 bf = *(const float4*)&Wt[k * 68 + c0];
            u64 b0 = splat2(bf.x), b1 = splat2(bf.y), b2 = splat2(bf.z), b3 = splat2(bf.w);
            ffma2(acc2[0][0], A0.x, b0); ffma2(acc2[0][1], A0.x, b1);
            ffma2(acc2[0][2], A0.x, b2); ffma2(acc2[0][3], A0.x, b3);
            ffma2(acc2[1][0], A0.y, b0); ffma2(acc2[1][1], A0.y, b1);
            ffma2(acc2[1][2], A0.y, b2); ffma2(acc2[1][3], A0.y, b3);
            ffma2(acc2[2][0], A1.x, b0); ffma2(acc2[2][1], A1.x, b1);
            ffma2(acc2[2][2], A1.x, b2); ffma2(acc2[2][3], A1.x, b3);
            ffma2(acc2[3][0], A1.y, b0); ffma2(acc2[3][1], A1.y, b1);
            ffma2(acc2[3][2], A1.y, b2); ffma2(acc2[3][3], A1.y, b3);
        }
        __syncthreads();
    }

    float acc[8][4];
#pragma unroll
    for (int u = 0; u < 4; u++)
#pragma unroll
        for (int j = 0; j < 4; j++) {
            float2 f = unpack2(acc2[u][j]);
            acc[2 * u + 0][j] = f.x;
            acc[2 * u + 1][j] = f.y;
        }

    if (which == 0) {
#pragma unroll
        for (int i = 0; i < 8; i++)
#pragma unroll
            for (int j = 0; j < 4; j++) acc[i][j] *= 0.125f;
    }

    if (which <= 1) {
        float* outT = (which == 0) ? g_Qt : g_Kt;
#pragma unroll
        for (int j = 0; j < 4; j++) {
            float4 lo = make_float4(acc[0][j], acc[1][j], acc[2][j], acc[3][j]);
            float4 hi = make_float4(acc[4][j], acc[5][j], acc[6][j], acc[7][j]);
            *(float4*)&outT[(size_t)(c0 + j) * MTOT + m0 + r0]     = lo;
            *(float4*)&outT[(size_t)(c0 + j) * MTOT + m0 + r0 + 4] = hi;
        }
    } else {
#pragma unroll
        for (int i = 0; i < 8; i++)
            *(float4*)&g_V[(size_t)(m0 + r0 + i) * HDIM + c0] =
                make_float4(acc[i][0], acc[i][1], acc[i][2], acc[i][3]);
    }
}

// ---------------------------------------------------------------------------
// Causal flash attention, split-KV. BM=BN=64, 256 threads, 4x4 tile/thread.
// grid.x = 64*NSPLIT (qb reversed: longest first), grid.y = B.
// Writes unnormalized partial O + (m, l) stats per split; merged afterwards.
// ---------------------------------------------------------------------------
__global__ __launch_bounds__(256, 3) void attn_kernel()
{
    extern __shared__ float sm[];
    float* Qt = sm;                 // [h][row]   64 x 68
    float* Kt = Qt + 64 * 68;       // [h][key]   64 x 68
    float* Vs = Kt + 64 * 68;       // [key][h]   64 x 68
    float* Pt = Vs + 64 * 68;       // [key][row] 64 x 64, swizzled

    const int b     = blockIdx.y;
    const int qb    = 63 - (blockIdx.x >> 1);   // longest CTAs first
    const int split = blockIdx.x & 1;
    const int nblk  = qb + 1;
    const int j0    = (nblk * split) >> 1;
    const int j1    = (nblk * (split + 1)) >> 1;

    const int tid = threadIdx.x;
    const int rg  = tid >> 4;        // 16 row-groups
    const int cg  = tid & 15;        // 16 col-groups
    const int r0  = rg * 4;
    const int c0  = cg * 4;
    const int m0  = b * TLEN + qb * 64;

    float* Op = g_Opart + (size_t)split * MTOT * HDIM;

    if (j0 == j1) {   // empty split: neutral partials
        float4 z = make_float4(0.f, 0.f, 0.f, 0.f);
#pragma unroll
        for (int i = 0; i < 4; i++)
            *(float4*)&Op[(size_t)(m0 + r0 + i) * HDIM + c0] = z;
        if (cg == 0)
#pragma unroll
            for (int i = 0; i < 4; i++)
                g_stats[split * MTOT + m0 + r0 + i] = make_float2(-1e30f, 0.f);
        return;
    }

    // Q tile (pre-scaled): [h][row]
#pragma unroll
    for (int l = 0; l < 4; l++) {
        int idx = tid + l * 256;
        int h = idx >> 4, p = idx & 15;
        *(float4*)&Qt[h * 68 + p * 4] = *(const float4*)&g_Qt[(size_t)h * MTOT + m0 + p * 4];
    }

    u64 o2[2][4];
    float mrow[4], lrow[4];
#pragma unroll
    for (int u = 0; u < 2; u++)
#pragma unroll
        for (int j = 0; j < 4; j++) o2[u][j] = 0ull;
#pragma unroll
    for (int i = 0; i < 4; i++) { mrow[i] = -1e30f; lrow[i] = 0.0f; }

    for (int jb = j0; jb < j1; jb++) {
        const int kb = b * TLEN + jb * 64;
#pragma unroll
        for (int l = 0; l < 4; l++) {
            int idx = tid + l * 256;
            int row = idx >> 4, p = idx & 15;
            *(float4*)&Kt[row * 68 + p * 4] = *(const float4*)&g_Kt[(size_t)row * MTOT + kb + p * 4];
            *(float4*)&Vs[row * 68 + p * 4] = *(const float4*)&g_V[(size_t)(kb + row) * HDIM + p * 4];
        }
        __syncthreads();

        // S = Q^T K (4 rows x 4 keys per thread)
        u64 s2[2][4];
#pragma unroll
        for (int u = 0; u < 2; u++)
#pragma unroll
            for (int j = 0; j < 4; j++) s2[u][j] = 0ull;

#pragma unroll 8
        for (int k = 0; k < 64; k++) {
            ulonglong2 A = *(const ulonglong2*)&Qt[k * 68 + r0];
            float4 bf = *(const float4*)&Kt[k * 68 + c0];
            u64 b0 = splat2(bf.x), b1 = splat2(bf.y), b2 = splat2(bf.z), b3 = splat2(bf.w);
            ffma2(s2[0][0], A.x, b0); ffma2(s2[0][1], A.x, b1);
            ffma2(s2[0][2], A.x, b2); ffma2(s2[0][3], A.x, b3);
            ffma2(s2[1][0], A.y, b0); ffma2(s2[1][1], A.y, b1);
            ffma2(s2[1][2], A.y, b2); ffma2(s2[1][3], A.y, b3);
        }

        float s[4][4];
#pragma unroll
        for (int u = 0; u < 2; u++)
#pragma unroll
            for (int j = 0; j < 4; j++) {
                float2 f = unpack2(s2[u][j]);
                s[2 * u + 0][j] = f.x;
                s[2 * u + 1][j] = f.y;
            }

        if (jb == qb) {
#pragma unroll
            for (int i = 0; i < 4; i++)
#pragma unroll
                for (int j = 0; j < 4; j++)
                    if (c0 + j > r0 + i) s[i][j] = -1e30f;
        }

        // Online softmax (row reductions across 16 lanes)
        float al[4], p[4][4];
#pragma unroll
        for (int i = 0; i < 4; i++) {
            float mloc = fmaxf(fmaxf(s[i][0], s[i][1]), fmaxf(s[i][2], s[i][3]));
#pragma unroll
            for (int d = 1; d < 16; d <<= 1)
                mloc = fmaxf(mloc, __shfl_xor_sync(0xffffffffu, mloc, d));
            float mn = fmaxf(mrow[i], mloc);
            al[i] = __expf(mrow[i] - mn);
            float rs = 0.0f;
#pragma unroll
            for (int j = 0; j < 4; j++) {
                p[i][j] = __expf(s[i][j] - mn);
                rs += p[i][j];
            }
#pragma unroll
            for (int d = 1; d < 16; d <<= 1)
                rs += __shfl_xor_sync(0xffffffffu, rs, d);
            lrow[i] = lrow[i] * al[i] + rs;
            mrow[i] = mn;
        }
#pragma unroll
        for (int u = 0; u < 2; u++) {
            u64 a2 = pack2(al[2 * u], al[2 * u + 1]);
#pragma unroll
            for (int j = 0; j < 4; j++) o2[u][j] = mul2(o2[u][j], a2);
        }

        // Store P transposed, swizzled on key bits [5:2] (distinct banks/lane)
#pragma unroll
        for (int j = 0; j < 4; j++) {
            int key = c0 + j;
            int sw  = (rg ^ (key >> 2)) << 2;
            *(float4*)&Pt[key * 64 + sw] = make_float4(p[0][j], p[1][j], p[2][j], p[3][j]);
        }
        __syncthreads();

        // O += P @ V
#pragma unroll 8
        for (int k = 0; k < 64; k++) {
            ulonglong2 A = *(const ulonglong2*)&Pt[k * 64 + ((rg ^ (k >> 2)) << 2)];
            float4 vf = *(const float4*)&Vs[k * 68 + c0];
            u64 b0 = splat2(vf.x), b1 = splat2(vf.y), b2 = splat2(vf.z), b3 = splat2(vf.w);
            ffma2(o2[0][0], A.x, b0); ffma2(o2[0][1], A.x, b1);
            ffma2(o2[0][2], A.x, b2); ffma2(o2[0][3], A.x, b3);
            ffma2(o2[1][0], A.y, b0); ffma2(o2[1][1], A.y, b1);
            ffma2(o2[1][2], A.y, b2); ffma2(o2[1][3], A.y, b3);
        }
        __syncthreads();
    }

    // Write unnormalized partial O + stats
    float o[4][4];
#pragma unroll
    for (int u = 0; u < 2; u++)
#pragma unroll
        for (int j = 0; j < 4; j++) {
            float2 f = unpack2(o2[u][j]);
            o[2 * u + 0][j] = f.x;
            o[2 * u + 1][j] = f.y;
        }
#pragma unroll
    for (int i = 0; i < 4; i++)
        *(float4*)&Op[(size_t)(m0 + r0 + i) * HDIM + c0] =
            make_float4(o[i][0], o[i][1], o[i][2], o[i][3]);
    if (cg == 0)
#pragma unroll
        for (int i = 0; i < 4; i++)
            g_stats[split * MTOT + m0 + r0 + i] = make_float2(mrow[i], lrow[i]);
}

// ---------------------------------------------------------------------------
// Merge the two split partials. One float4 per thread over [MTOT, H].
// ---------------------------------------------------------------------------
__global__ __launch_bounds__(256) void merge_kernel(float* __restrict__ out)
{
    int idx = blockIdx.x * 256 + threadIdx.x;       // MTOT*16 threads
    int m = idx >> 4;
    int h = (idx & 15) * 4;

    float2 s0 = g_stats[m];
    float2 s1 = g_stats[MTOT + m];
    float mm = fmaxf(s0.x, s1.x);
    float a0 = __expf(s0.x - mm);
    float a1 = __expf(s1.x - mm);
    float rinv = 1.0f / (s0.y * a0 + s1.y * a1);

    float4 o0 = *(const float4*)&g_Opart[(size_t)m * HDIM + h];
    float4 o1 = *(const float4*)&g_Opart[(size_t)(MTOT + m) * HDIM + h];

    float4 r;
    r.x = (o0.x * a0 + o1.x * a1) * rinv;
    r.y = (o0.y * a0 + o1.y * a1) * rinv;
    r.z = (o0.z * a0 + o1.z * a1) * rinv;
    r.w = (o0.w * a0 + o1.w * a1) * rinv;
    *(float4*)&out[(size_t)m * HDIM + h] = r;
}

// ---------------------------------------------------------------------------
extern "C" void kernel_launch(void* const* d_in, const int* in_sizes, int n_in,
                              void* d_out, int out_size)
{
    const float* x  = (const float*)d_in[0];
    const float* Wk = (const float*)d_in[2];
    const float* Wq = (const float*)d_in[3];
    const float* Wv = (const float*)d_in[4];
    float* out = (float*)d_out;

    dim3 gp(128, 3);
    proj_kernel<<<gp, 256>>>(x, Wk, Wq, Wv);

    const int smem_bytes = (3 * 64 * 68 + 64 * 64) * (int)sizeof(float);  // 68608
    cudaFuncSetAttribute(attn_kernel,
                         cudaFuncAttributeMaxDynamicSharedMemorySize, smem_bytes);
    dim3 ga(64 * NSPLIT, 4);
    attn_kernel<<<ga, 256, smem_bytes>>>();

    merge_kernel<<<(MTOT * 16) / 256, 256>>>(out);
}

// round 4
// speedup vs baseline: 1.3351x; 1.0042x over previous
#include <cuda_runtime.h>
#include <math.h>

#define BSZ  4
#define TLEN 4096
#define CDIM 1024
#define HDIM 64
#define MTOT (BSZ * TLEN)
#define NSPLIT 2

// Projected operands. Q and K stored TRANSPOSED [h][m]; Q pre-scaled by H^-0.5.
__device__ float g_Qt[HDIM * MTOT];
__device__ float g_Kt[HDIM * MTOT];
__device__ float g_V [MTOT * HDIM];
// Split-KV partials: unnormalized O and (m, l) stats per split.
__device__ float  g_Opart[NSPLIT * MTOT * HDIM];
__device__ float2 g_stats[NSPLIT * MTOT];

typedef unsigned long long u64;

__device__ __forceinline__ u64 splat2(float x) {
    u64 r; asm("mov.b64 %0, {%1, %1};" : "=l"(r) : "f"(x)); return r;
}
__device__ __forceinline__ u64 pack2(float x, float y) {
    u64 r; asm("mov.b64 %0, {%1, %2};" : "=l"(r) : "f"(x), "f"(y)); return r;
}
__device__ __forceinline__ float2 unpack2(u64 v) {
    float2 f; asm("mov.b64 {%0, %1}, %2;" : "=f"(f.x), "=f"(f.y) : "l"(v)); return f;
}
__device__ __forceinline__ void ffma2(u64 &d, u64 a, u64 b) {
    asm("fma.rn.f32x2 %0, %1, %2, %0;" : "+l"(d) : "l"(a), "l"(b));
}
__device__ __forceinline__ u64 mul2(u64 a, u64 b) {
    u64 r; asm("mul.rn.f32x2 %0, %1, %2;" : "=l"(r) : "l"(a), "l"(b)); return r;
}

// ---------------------------------------------------------------------------
// Projection (unchanged; at fp32 roofline). out[m,h] = sum_c x[m,c]*W[h,c].
// ---------------------------------------------------------------------------
__global__ __launch_bounds__(256) void proj_kernel(
    const float* __restrict__ x,
    const float* __restrict__ Wk,
    const float* __restrict__ Wq,
    const float* __restrict__ Wv)
{
    __shared__ float Xt[32 * 128];
    __shared__ float Wt[32 * 68];

    const int which = blockIdx.y;
    const float* __restrict__ W = (which == 0) ? Wq : (which == 1) ? Wk : Wv;

    const int m0  = blockIdx.x * 128;
    const int tid = threadIdx.x;
    const int r0  = (tid >> 4) * 8;
    const int c0  = (tid & 15) * 4;
    const int rg  = r0 >> 2;

    u64 acc2[4][4];
#pragma unroll
    for (int u = 0; u < 4; u++)
#pragma unroll
        for (int j = 0; j < 4; j++) acc2[u][j] = 0ull;

    for (int kc = 0; kc < CDIM; kc += 32) {
#pragma unroll
        for (int l = 0; l < 4; l++) {
            int idx = tid + l * 256;
            int row = idx >> 3;
            int p   = idx & 7;
            float4 v = *(const float4*)(x + (size_t)(m0 + row) * CDIM + kc + p * 4);
            int mg = row >> 2, ml = row & 3;
            int cc = p * 4;
            Xt[(cc + 0) * 128 + ((mg ^ (cc + 0)) << 2) + ml] = v.x;
            Xt[(cc + 1) * 128 + ((mg ^ (cc + 1)) << 2) + ml] = v.y;
            Xt[(cc + 2) * 128 + ((mg ^ (cc + 2)) << 2) + ml] = v.z;
            Xt[(cc + 3) * 128 + ((mg ^ (cc + 3)) << 2) + ml] = v.w;
        }
#pragma unroll
        for (int l = 0; l < 2; l++) {
            int idx = tid + l * 256;
            int row = idx >> 3;
            int p   = idx & 7;
            float4 v = *(const float4*)(W + (size_t)row * CDIM + kc + p * 4);
            Wt[(p * 4 + 0) * 68 + row] = v.x;
            Wt[(p * 4 + 1) * 68 + row] = v.y;
            Wt[(p * 4 + 2) * 68 + row] = v.z;
            Wt[(p * 4 + 3) * 68 + row] = v.w;
        }
        __syncthreads();

#pragma unroll 8
        for (int k = 0; k < 32; k++) {
            ulonglong2 A0 = *(const ulonglong2*)&Xt[k * 128 + ((rg ^ k) << 2)];
            ulonglong2 A1 = *(const ulonglong2*)&Xt[k * 128 + (((rg + 1) ^ k) << 2)];
            float4 bf = *(const float4*)&Wt[k * 68 + c0];
            u64 b0 = splat2(bf.x), b1 = splat2(bf.y), b2 = splat2(bf.z), b3 = splat2(bf.w);
            ffma2(acc2[0][0], A0.x, b0); ffma2(acc2[0][1], A0.x, b1);
            ffma2(acc2[0][2], A0.x, b2); ffma2(acc2[0][3], A0.x, b3);
            ffma2(acc2[1][0], A0.y, b0); ffma2(acc2[1][1], A0.y, b1);
            ffma2(acc2[1][2], A0.y, b2); ffma2(acc2[1][3], A0.y, b3);
            ffma2(acc2[2][0], A1.x, b0); ffma2(acc2[2][1], A1.x, b1);
            ffma2(acc2[2][2], A1.x, b2); ffma2(acc2[2][3], A1.x, b3);
            ffma2(acc2[3][0], A1.y, b0); ffma2(acc2[3][1], A1.y, b1);
            ffma2(acc2[3][2], A1.y, b2); ffma2(acc2[3][3], A1.y, b3);
        }
        __syncthreads();
    }

    float acc[8][4];
#pragma unroll
    for (int u = 0; u < 4; u++)
#pragma unroll
        for (int j = 0; j < 4; j++) {
            float2 f = unpack2(acc2[u][j]);
            acc[2 * u + 0][j] = f.x;
            acc[2 * u + 1][j] = f.y;
        }

    if (which == 0) {
#pragma unroll
        for (int i = 0; i < 8; i++)
#pragma unroll
            for (int j = 0; j < 4; j++) acc[i][j] *= 0.125f;
    }

    if (which <= 1) {
        float* outT = (which == 0) ? g_Qt : g_Kt;
#pragma unroll
        for (int j = 0; j < 4; j++) {
            float4 lo = make_float4(acc[0][j], acc[1][j], acc[2][j], acc[3][j]);
            float4 hi = make_float4(acc[4][j], acc[5][j], acc[6][j], acc[7][j]);
            *(float4*)&outT[(size_t)(c0 + j) * MTOT + m0 + r0]     = lo;
            *(float4*)&outT[(size_t)(c0 + j) * MTOT + m0 + r0 + 4] = hi;
        }
    } else {
#pragma unroll
        for (int i = 0; i < 8; i++)
            *(float4*)&g_V[(size_t)(m0 + r0 + i) * HDIM + c0] =
                make_float4(acc[i][0], acc[i][1], acc[i][2], acc[i][3]);
    }
}

// ---------------------------------------------------------------------------
// Causal flash attention, split-KV. BM=BN=64, 256 threads, 4x4 tile/thread.
// grid.x = 64*NSPLIT (qb reversed: longest first), grid.y = B.
// Writes unnormalized partial O + (m, l) stats per split; merged afterwards.
// ---------------------------------------------------------------------------
__global__ __launch_bounds__(256, 3) void attn_kernel()
{
    extern __shared__ float sm[];
    float* Qt = sm;                 // [h][row]   64 x 68
    float* Kt = Qt + 64 * 68;       // [h][key]   64 x 68
    float* Vs = Kt + 64 * 68;       // [key][h]   64 x 68
    float* Pt = Vs + 64 * 68;       // [key][row] 64 x 64, swizzled

    const int b     = blockIdx.y;
    const int qb    = 63 - (blockIdx.x >> 1);   // longest CTAs first
    const int split = blockIdx.x & 1;
    const int nblk  = qb + 1;
    const int j0    = (nblk * split) >> 1;
    const int j1    = (nblk * (split + 1)) >> 1;

    const int tid = threadIdx.x;
    const int rg  = tid >> 4;        // 16 row-groups
    const int cg  = tid & 15;        // 16 col-groups
    const int r0  = rg * 4;
    const int c0  = cg * 4;
    const int m0  = b * TLEN + qb * 64;

    float* Op = g_Opart + (size_t)split * MTOT * HDIM;

    if (j0 == j1) {   // empty split: neutral partials
        float4 z = make_float4(0.f, 0.f, 0.f, 0.f);
#pragma unroll
        for (int i = 0; i < 4; i++)
            *(float4*)&Op[(size_t)(m0 + r0 + i) * HDIM + c0] = z;
        if (cg == 0)
#pragma unroll
            for (int i = 0; i < 4; i++)
                g_stats[split * MTOT + m0 + r0 + i] = make_float2(-1e30f, 0.f);
        return;
    }

    // Q tile (pre-scaled): [h][row]
#pragma unroll
    for (int l = 0; l < 4; l++) {
        int idx = tid + l * 256;
        int h = idx >> 4, p = idx & 15;
        *(float4*)&Qt[h * 68 + p * 4] = *(const float4*)&g_Qt[(size_t)h * MTOT + m0 + p * 4];
    }

    u64 o2[2][4];
    float mrow[4], lrow[4];
#pragma unroll
    for (int u = 0; u < 2; u++)
#pragma unroll
        for (int j = 0; j < 4; j++) o2[u][j] = 0ull;
#pragma unroll
    for (int i = 0; i < 4; i++) { mrow[i] = -1e30f; lrow[i] = 0.0f; }

    for (int jb = j0; jb < j1; jb++) {
        const int kb = b * TLEN + jb * 64;
#pragma unroll
        for (int l = 0; l < 4; l++) {
            int idx = tid + l * 256;
            int row = idx >> 4, p = idx & 15;
            *(float4*)&Kt[row * 68 + p * 4] = *(const float4*)&g_Kt[(size_t)row * MTOT + kb + p * 4];
            *(float4*)&Vs[row * 68 + p * 4] = *(const float4*)&g_V[(size_t)(kb + row) * HDIM + p * 4];
        }
        __syncthreads();

        // S = Q^T K (4 rows x 4 keys per thread)
        u64 s2[2][4];
#pragma unroll
        for (int u = 0; u < 2; u++)
#pragma unroll
            for (int j = 0; j < 4; j++) s2[u][j] = 0ull;

#pragma unroll 8
        for (int k = 0; k < 64; k++) {
            ulonglong2 A = *(const ulonglong2*)&Qt[k * 68 + r0];
            float4 bf = *(const float4*)&Kt[k * 68 + c0];
            u64 b0 = splat2(bf.x), b1 = splat2(bf.y), b2 = splat2(bf.z), b3 = splat2(bf.w);
            ffma2(s2[0][0], A.x, b0); ffma2(s2[0][1], A.x, b1);
            ffma2(s2[0][2], A.x, b2); ffma2(s2[0][3], A.x, b3);
            ffma2(s2[1][0], A.y, b0); ffma2(s2[1][1], A.y, b1);
            ffma2(s2[1][2], A.y, b2); ffma2(s2[1][3], A.y, b3);
        }

        float s[4][4];
#pragma unroll
        for (int u = 0; u < 2; u++)
#pragma unroll
            for (int j = 0; j < 4; j++) {
                float2 f = unpack2(s2[u][j]);
                s[2 * u + 0][j] = f.x;
                s[2 * u + 1][j] = f.y;
            }

        if (jb == qb) {
#pragma unroll
            for (int i = 0; i < 4; i++)
#pragma unroll
                for (int j = 0; j < 4; j++)
                    if (c0 + j > r0 + i) s[i][j] = -1e30f;
        }

        // Online softmax (row reductions across 16 lanes)
        float al[4], p[4][4];
#pragma unroll
        for (int i = 0; i < 4; i++) {
            float mloc = fmaxf(fmaxf(s[i][0], s[i][1]), fmaxf(s[i][2], s[i][3]));
#pragma unroll
            for (int d = 1; d < 16; d <<= 1)
                mloc = fmaxf(mloc, __shfl_xor_sync(0xffffffffu, mloc, d));
            float mn = fmaxf(mrow[i], mloc);
            al[i] = __expf(mrow[i] - mn);
            float rs = 0.0f;
#pragma unroll
            for (int j = 0; j < 4; j++) {
                p[i][j] = __expf(s[i][j] - mn);
                rs += p[i][j];
            }
#pragma unroll
            for (int d = 1; d < 16; d <<= 1)
                rs += __shfl_xor_sync(0xffffffffu, rs, d);
            lrow[i] = lrow[i] * al[i] + rs;
            mrow[i] = mn;
        }
#pragma unroll
        for (int u = 0; u < 2; u++) {
            u64 a2 = pack2(al[2 * u], al[2 * u + 1]);
#pragma unroll
            for (int j = 0; j < 4; j++) o2[u][j] = mul2(o2[u][j], a2);
        }

        // Store P transposed, swizzled on key bits [5:2] (distinct banks/lane)
#pragma unroll
        for (int j = 0; j < 4; j++) {
            int key = c0 + j;
            int sw  = (rg ^ (key >> 2)) << 2;
            *(float4*)&Pt[key * 64 + sw] = make_float4(p[0][j], p[1][j], p[2][j], p[3][j]);
        }
        __syncthreads();

        // O += P @ V
#pragma unroll 8
        for (int k = 0; k < 64; k++) {
            ulonglong2 A = *(const ulonglong2*)&Pt[k * 64 + ((rg ^ (k >> 2)) << 2)];
            float4 vf = *(const float4*)&Vs[k * 68 + c0];
            u64 b0 = splat2(vf.x), b1 = splat2(vf.y), b2 = splat2(vf.z), b3 = splat2(vf.w);
            ffma2(o2[0][0], A.x, b0); ffma2(o2[0][1], A.x, b1);
            ffma2(o2[0][2], A.x, b2); ffma2(o2[0][3], A.x, b3);
            ffma2(o2[1][0], A.y, b0); ffma2(o2[1][1], A.y, b1);
            ffma2(o2[1][2], A.y, b2); ffma2(o2[1][3], A.y, b3);
        }
        __syncthreads();
    }

    // Write unnormalized partial O + stats
    float o[4][4];
#pragma unroll
    for (int u = 0; u < 2; u++)
#pragma unroll
        for (int j = 0; j < 4; j++) {
            float2 f = unpack2(o2[u][j]);
            o[2 * u + 0][j] = f.x;
            o[2 * u + 1][j] = f.y;
        }
#pragma unroll
    for (int i = 0; i < 4; i++)
        *(float4*)&Op[(size_t)(m0 + r0 + i) * HDIM + c0] =
            make_float4(o[i][0], o[i][1], o[i][2], o[i][3]);
    if (cg == 0)
#pragma unroll
        for (int i = 0; i < 4; i++)
            g_stats[split * MTOT + m0 + r0 + i] = make_float2(mrow[i], lrow[i]);
}

// ---------------------------------------------------------------------------
// Merge the two split partials. One float4 per thread over [MTOT, H].
// ---------------------------------------------------------------------------
__global__ __launch_bounds__(256) void merge_kernel(float* __restrict__ out)
{
    int idx = blockIdx.x * 256 + threadIdx.x;       // MTOT*16 threads
    int m = idx >> 4;
    int h = (idx & 15) * 4;

    float2 s0 = g_stats[m];
    float2 s1 = g_stats[MTOT + m];
    float mm = fmaxf(s0.x, s1.x);
    float a0 = __expf(s0.x - mm);
    float a1 = __expf(s1.x - mm);
    float rinv = 1.0f / (s0.y * a0 + s1.y * a1);

    float4 o0 = *(const float4*)&g_Opart[(size_t)m * HDIM + h];
    float4 o1 = *(const float4*)&g_Opart[(size_t)(MTOT + m) * HDIM + h];

    float4 r;
    r.x = (o0.x * a0 + o1.x * a1) * rinv;
    r.y = (o0.y * a0 + o1.y * a1) * rinv;
    r.z = (o0.z * a0 + o1.z * a1) * rinv;
    r.w = (o0.w * a0 + o1.w * a1) * rinv;
    *(float4*)&out[(size_t)m * HDIM + h] = r;
}

// ---------------------------------------------------------------------------
extern "C" void kernel_launch(void* const* d_in, const int* in_sizes, int n_in,
                              void* d_out, int out_size)
{
    const float* x  = (const float*)d_in[0];
    const float* Wk = (const float*)d_in[2];
    const float* Wq = (const float*)d_in[3];
    const float* Wv = (const float*)d_in[4];
    float* out = (float*)d_out;

    dim3 gp(128, 3);
    proj_kernel<<<gp, 256>>>(x, Wk, Wq, Wv);

    const int smem_bytes = (3 * 64 * 68 + 64 * 64) * (int)sizeof(float);  // 68608
    cudaFuncSetAttribute(attn_kernel,
                         cudaFuncAttributeMaxDynamicSharedMemorySize, smem_bytes);
    dim3 ga(64 * NSPLIT, 4);
    attn_kernel<<<ga, 256, smem_bytes>>>();

    merge_kernel<<<(MTOT * 16) / 256, 256>>>(out);
}